// round 15
// baseline (speedup 1.0000x reference)
#include <cuda_runtime.h>
#include <cuda_bf16.h>
#include <math.h>
#include <stdint.h>

// Problem constants
#define S    2048
#define HID  2048
#define NH   32
#define NKV  8
#define HD   64
#define QD   (NH*HD)    // 2048
#define KVD  (NKV*HD)   // 512

#define BIG_N   (4194304)
#define SMALL_N (1048576)

// Scratch (device globals: allocation-free rule)
__device__ float g_Q[S * QD];
__device__ float g_K[S * KVD];
__device__ float g_V[S * KVD];

// RoPE trig tables
__device__ float g_cos[S * 32];
__device__ float g_sin[S * 32];

// bf16 split slabs. X/Wq/Wk/Wv/Wo/A as before; K/V (post-rope) at 18M/19M.
#define OFF_X   0
#define OFF_WQ  (4*1024*1024)
#define OFF_WK  (8*1024*1024)
#define OFF_WV  (9*1024*1024)
#define OFF_WO  (10*1024*1024)
#define OFF_A   (14*1024*1024)
#define OFF_K   (18*1024*1024)
#define OFF_V   (19*1024*1024)
#define IN_TOTAL (14*1024*1024)
#define SLAB_N  (20*1024*1024)
__device__ __nv_bfloat16 g_s0[SLAB_N];
__device__ __nv_bfloat16 g_s1[SLAB_N];

// Role table: 0=hidden(X), 1=Wq, 2=Wk, 3=Wv, 4=Wo, 5=Mask
__device__ const float* g_role[6];

// ---------------------------------------------------------------------------
// Input classification (verified rounds 3-14).
// ---------------------------------------------------------------------------
__global__ void classify_kernel(const float* b0, const float* b1,
                                const float* b2, const float* b3,
                                const float* s0, const float* s1)
{
    const int lane = threadIdx.x;
    const float* bigs[4] = {b0, b1, b2, b3};
    float mx[4];
    #pragma unroll
    for (int i = 0; i < 4; i++) {
        float v = fmaxf(fabsf(bigs[i][lane]), fabsf(bigs[i][lane + 32]));
        #pragma unroll
        for (int off = 16; off > 0; off >>= 1)
            v = fmaxf(v, __shfl_xor_sync(0xFFFFFFFFu, v, off));
        mx[i] = v;
    }
    if (lane == 0) {
        int mask_i = -1, hid_i = -1;
        for (int i = 0; i < 4; i++)
            if (bigs[i][0] == 0.0f && bigs[i][1] <= -1e8f) { mask_i = i; break; }
        for (int i = 0; i < 4; i++) {
            if (i == mask_i) continue;
            if (mx[i] > 0.3f) { hid_i = i; break; }
        }
        if (mask_i < 0 || hid_i < 0 || mask_i == hid_i) { hid_i = 0; mask_i = 3; }

        int r0 = -1, r1 = -1;
        for (int i = 0; i < 4; i++)
            if (i != mask_i && i != hid_i) { if (r0 < 0) r0 = i; else r1 = i; }
        int wq_i, wo_i;
        if (hid_i == 0) { wq_i = r0; wo_i = r1; }
        else            { wo_i = r0; wq_i = r1; }

        g_role[0] = bigs[hid_i];
        g_role[1] = bigs[wq_i];
        g_role[2] = s0;
        g_role[3] = s1;
        g_role[4] = bigs[wo_i];
        g_role[5] = bigs[mask_i];
    }
}

// ---------------------------------------------------------------------------
// RoPE trig table.
// ---------------------------------------------------------------------------
__global__ void trig_kernel()
{
    int idx = blockIdx.x * blockDim.x + threadIdx.x;
    if (idx >= S * 32) return;
    int i = idx & 31;
    int s = idx >> 5;
    double invf = pow(10000.0, -(double)(2 * i) / 64.0);
    double ang = (double)s * invf;
    g_cos[idx] = (float)cos(ang);
    g_sin[idx] = (float)sin(ang);
}

// ---------------------------------------------------------------------------
// Fused split of ALL inputs into bf16 (hi, lo) slabs.
// ---------------------------------------------------------------------------
__global__ void split_all_kernel()
{
    int idx4 = (blockIdx.x * blockDim.x + threadIdx.x) * 4;
    if (idx4 >= IN_TOTAL) return;
    int role, base;
    if      (idx4 < OFF_WQ) { role = 0; base = OFF_X;  }
    else if (idx4 < OFF_WK) { role = 1; base = OFF_WQ; }
    else if (idx4 < OFF_WV) { role = 2; base = OFF_WK; }
    else if (idx4 < OFF_WO) { role = 3; base = OFF_WV; }
    else                    { role = 4; base = OFF_WO; }
    const float* __restrict__ src = g_role[role] + (idx4 - base);

    float4 x = *(const float4*)src;
    __nv_bfloat16 h0 = __float2bfloat16(x.x);
    __nv_bfloat16 h1 = __float2bfloat16(x.y);
    __nv_bfloat16 h2 = __float2bfloat16(x.z);
    __nv_bfloat16 h3 = __float2bfloat16(x.w);
    __nv_bfloat162 hi01 = {h0, h1}, hi23 = {h2, h3}, lo01, lo23;
    lo01.x = __float2bfloat16(x.x - __bfloat162float(h0));
    lo01.y = __float2bfloat16(x.y - __bfloat162float(h1));
    lo23.x = __float2bfloat16(x.z - __bfloat162float(h2));
    lo23.y = __float2bfloat16(x.w - __bfloat162float(h3));
    *(__nv_bfloat162*)(g_s0 + idx4)     = hi01;
    *(__nv_bfloat162*)(g_s0 + idx4 + 2) = hi23;
    *(__nv_bfloat162*)(g_s1 + idx4)     = lo01;
    *(__nv_bfloat162*)(g_s1 + idx4 + 2) = lo23;
}

// ---------------------------------------------------------------------------
// Split post-rope K and V (fp32 scratch) into bf16 hi/lo slabs.
// ---------------------------------------------------------------------------
__global__ void split_kv_kernel()
{
    int idx4 = (blockIdx.x * blockDim.x + threadIdx.x) * 4;
    if (idx4 >= 2 * SMALL_N) return;
    const float* src;
    int off;
    if (idx4 < SMALL_N) { src = g_K + idx4;           off = OFF_K + idx4; }
    else                { src = g_V + idx4 - SMALL_N; off = OFF_V + idx4 - SMALL_N; }

    float4 x = *(const float4*)src;
    __nv_bfloat16 h0 = __float2bfloat16(x.x);
    __nv_bfloat16 h1 = __float2bfloat16(x.y);
    __nv_bfloat16 h2 = __float2bfloat16(x.z);
    __nv_bfloat16 h3 = __float2bfloat16(x.w);
    __nv_bfloat162 hi01 = {h0, h1}, hi23 = {h2, h3}, lo01, lo23;
    lo01.x = __float2bfloat16(x.x - __bfloat162float(h0));
    lo01.y = __float2bfloat16(x.y - __bfloat162float(h1));
    lo23.x = __float2bfloat16(x.z - __bfloat162float(h2));
    lo23.y = __float2bfloat16(x.w - __bfloat162float(h3));
    *(__nv_bfloat162*)(g_s0 + off)     = hi01;
    *(__nv_bfloat162*)(g_s0 + off + 2) = hi23;
    *(__nv_bfloat162*)(g_s1 + off)     = lo01;
    *(__nv_bfloat162*)(g_s1 + off + 2) = lo23;
}

// ---------------------------------------------------------------------------
// helpers
// ---------------------------------------------------------------------------
__device__ __forceinline__ uint32_t smem_u32(const void* p) {
    return (uint32_t)__cvta_generic_to_shared(p);
}
__device__ __forceinline__ void cp_async16_s(uint32_t saddr, const void* g) {
    asm volatile("cp.async.ca.shared.global [%0], [%1], 16;\n" :: "r"(saddr), "l"(g));
}
__device__ __forceinline__ void cp_async16(void* smem, const void* gmem) {
    cp_async16_s(smem_u32(smem), gmem);
}
#define CP_COMMIT()  asm volatile("cp.async.commit_group;\n")
#define CP_WAIT(n)   asm volatile("cp.async.wait_group %0;\n" :: "n"(n))

__device__ __forceinline__ void mma_bf16(float d[4], const uint32_t a[4], const uint32_t b[2])
{
    asm volatile(
        "mma.sync.aligned.m16n8k16.row.col.f32.bf16.bf16.f32 "
        "{%0,%1,%2,%3}, {%4,%5,%6,%7}, {%8,%9}, {%0,%1,%2,%3};\n"
        : "+f"(d[0]), "+f"(d[1]), "+f"(d[2]), "+f"(d[3])
        : "r"(a[0]), "r"(a[1]), "r"(a[2]), "r"(a[3]), "r"(b[0]), "r"(b[1]));
}

__device__ __forceinline__ void ldsm_x4(uint32_t r[4], const void* p) {
    uint32_t s = smem_u32(p);
    asm volatile("ldmatrix.sync.aligned.m8n8.x4.shared.b16 {%0,%1,%2,%3}, [%4];\n"
                 : "=r"(r[0]), "=r"(r[1]), "=r"(r[2]), "=r"(r[3]) : "r"(s));
}
__device__ __forceinline__ void ldsm_x4_trans(uint32_t r[4], const void* p) {
    uint32_t s = smem_u32(p);
    asm volatile("ldmatrix.sync.aligned.m8n8.x4.trans.shared.b16 {%0,%1,%2,%3}, [%4];\n"
                 : "=r"(r[0]), "=r"(r[1]), "=r"(r[2]), "=r"(r[3]) : "r"(s));
}

__device__ __forceinline__ void pack_hilo(float x, float y, uint32_t& hi, uint32_t& lo) {
    __nv_bfloat16 hx = __float2bfloat16(x);
    __nv_bfloat16 hy = __float2bfloat16(y);
    __nv_bfloat162 h = {hx, hy};
    __nv_bfloat162 l;
    l.x = __float2bfloat16(x - __bfloat162float(hx));
    l.y = __float2bfloat16(y - __bfloat162float(hy));
    hi = *(uint32_t*)&h;
    lo = *(uint32_t*)&l;
}

// ---------------------------------------------------------------------------
// bf16x3 GEMM, BK=32, 2-stage cp.async pipeline (verified round 14).
// ---------------------------------------------------------------------------
#define GEMM_SMEM_BYTES ((2*2*128*40 + 2*2*32*136) * 2)   // 75776

__global__ __launch_bounds__(256, 2) void gemm_bf16x3(
    float* outC, int mode)
{
    const int K = HID;
    const __nv_bfloat16 *A0g, *A1g, *B0, *B1;
    float* C;
    int N, cx;
    if (mode == 0) {
        A0g = g_s0 + OFF_X; A1g = g_s1 + OFF_X;
        const int bx = blockIdx.x;
        if (bx < 16)      { B0 = g_s0 + OFF_WQ; B1 = g_s1 + OFF_WQ; C = g_Q; N = QD;  cx = bx; }
        else if (bx < 20) { B0 = g_s0 + OFF_WK; B1 = g_s1 + OFF_WK; C = g_K; N = KVD; cx = bx - 16; }
        else              { B0 = g_s0 + OFF_WV; B1 = g_s1 + OFF_WV; C = g_V; N = KVD; cx = bx - 20; }
    } else {
        A0g = g_s0 + OFF_A; A1g = g_s1 + OFF_A;
        B0 = g_s0 + OFF_WO; B1 = g_s1 + OFF_WO;
        C = outC; N = HID; cx = blockIdx.x;
    }

    extern __shared__ __nv_bfloat16 smem[];
    __nv_bfloat16* AsB = smem;                    // [st][comp][128][40]
    __nv_bfloat16* BsB = smem + 2 * 2 * 128 * 40; // [st][comp][32][136]
#define AS(st, c, r) (AsB + (((st) * 2 + (c)) * 128 + (r)) * 40)
#define BS(st, c, r) (BsB + (((st) * 2 + (c)) * 32  + (r)) * 136)

    const int tid  = threadIdx.x;
    const int lane = tid & 31;
    const int warp = tid >> 5;
    const int wm = warp >> 2;
    const int wn = warp & 3;
    const int g  = lane >> 2;
    const int t  = lane & 3;

    const int am = tid >> 1,  ac = (tid & 1) * 16;
    const int bk = tid >> 3,  bn = (tid & 7) * 8;

    const __nv_bfloat16* Ag0 = A0g + (size_t)(blockIdx.y * 128 + am) * K + ac;
    const __nv_bfloat16* Ag1 = A1g + (size_t)(blockIdx.y * 128 + am) * K + ac;
    const __nv_bfloat16* Bg0 = B0 + (size_t)bk * N + cx * 128 + bn;
    const __nv_bfloat16* Bg1 = B1 + (size_t)bk * N + cx * 128 + bn;

    float acc[4][4][4];
    #pragma unroll
    for (int i = 0; i < 4; i++)
        #pragma unroll
        for (int j = 0; j < 4; j++)
            #pragma unroll
            for (int r = 0; r < 4; r++) acc[i][j][r] = 0.f;

#define STAGE_LOAD(st, kk) do {                                              \
        cp_async16(AS(st, 0, am) + ac,     Ag0 + (kk));                      \
        cp_async16(AS(st, 0, am) + ac + 8, Ag0 + (kk) + 8);                  \
        cp_async16(AS(st, 1, am) + ac,     Ag1 + (kk));                      \
        cp_async16(AS(st, 1, am) + ac + 8, Ag1 + (kk) + 8);                  \
        cp_async16(BS(st, 0, bk) + bn,      Bg0 + (size_t)(kk) * N);         \
        cp_async16(BS(st, 0, bk) + bn + 64, Bg0 + (size_t)(kk) * N + 64);    \
        cp_async16(BS(st, 1, bk) + bn,      Bg1 + (size_t)(kk) * N);         \
        cp_async16(BS(st, 1, bk) + bn + 64, Bg1 + (size_t)(kk) * N + 64);    \
    } while (0)

    STAGE_LOAD(0, 0);
    CP_COMMIT();

    const int li  = lane & 7;
    const int a_r = ((lane >> 3) & 1) * 8 + li;
    const int a_c = ((lane >> 3) >> 1) * 8;
    const int b_r = ((lane >> 3) & 1) * 8 + li;
    const int b_c = ((lane >> 3) >> 1) * 8;

    int buf = 0;
    for (int k0 = 0; k0 < K; k0 += 32, buf ^= 1) {
        if (k0 + 32 < K) {
            STAGE_LOAD(buf ^ 1, k0 + 32);
            CP_COMMIT();
            CP_WAIT(1);
        } else {
            CP_WAIT(0);
        }
        __syncthreads();

        #pragma unroll
        for (int ks = 0; ks < 2; ks++) {
            const int kc = ks * 16;
            uint32_t a0f[4][4], a1f[4][4];
            #pragma unroll
            for (int mt = 0; mt < 4; mt++) {
                const int r = wm * 64 + mt * 16 + a_r;
                ldsm_x4(a0f[mt], AS(buf, 0, r) + kc + a_c);
                ldsm_x4(a1f[mt], AS(buf, 1, r) + kc + a_c);
            }
            uint32_t b0f[4][2], b1f[4][2];
            #pragma unroll
            for (int p = 0; p < 2; p++) {
                const int c = wn * 32 + p * 16 + b_c;
                uint32_t r4[4];
                ldsm_x4_trans(r4, BS(buf, 0, kc + b_r) + c);
                b0f[2*p][0] = r4[0]; b0f[2*p][1] = r4[1];
                b0f[2*p+1][0] = r4[2]; b0f[2*p+1][1] = r4[3];
                ldsm_x4_trans(r4, BS(buf, 1, kc + b_r) + c);
                b1f[2*p][0] = r4[0]; b1f[2*p][1] = r4[1];
                b1f[2*p+1][0] = r4[2]; b1f[2*p+1][1] = r4[3];
            }

            #pragma unroll
            for (int mt = 0; mt < 4; mt++)
                #pragma unroll
                for (int nt = 0; nt < 4; nt++) {
                    mma_bf16(acc[mt][nt], a0f[mt], b0f[nt]);
                    mma_bf16(acc[mt][nt], a0f[mt], b1f[nt]);
                    mma_bf16(acc[mt][nt], a1f[mt], b0f[nt]);
                }
        }
        __syncthreads();
    }
#undef STAGE_LOAD
#undef AS
#undef BS

    #pragma unroll
    for (int mt = 0; mt < 4; mt++)
        #pragma unroll
        for (int nt = 0; nt < 4; nt++) {
            const int r = blockIdx.y * 128 + wm * 64 + mt * 16 + g;
            const int c = cx * 128 + wn * 32 + nt * 8 + 2 * t;
            *(float2*)(C + (size_t)r * N + c)       = make_float2(acc[mt][nt][0], acc[mt][nt][1]);
            *(float2*)(C + (size_t)(r + 8) * N + c) = make_float2(acc[mt][nt][2], acc[mt][nt][3]);
        }
}

// ---------------------------------------------------------------------------
// RoPE apply (table-driven).
// ---------------------------------------------------------------------------
__global__ void rope_apply(float* __restrict__ X, int nheads)
{
    int idx = blockIdx.x * blockDim.x + threadIdx.x;
    if (idx >= S * nheads * 32) return;
    int i = idx & 31;
    int t2 = idx >> 5;
    int h = t2 % nheads;
    int s = t2 / nheads;

    float c  = g_cos[(s << 5) + i];
    float sn = g_sin[(s << 5) + i];

    float* p = X + (size_t)s * (nheads * 64) + h * 64;
    float x1 = p[i];
    float x2 = p[i + 32];
    p[i]      = x1 * c - x2 * sn;
    p[i + 32] = x2 * c + x1 * sn;
}

// ---------------------------------------------------------------------------
// bf16x3 HMMA causal GQA flash attention.
// K/V staged from precomputed bf16 hi/lo slabs via cp.async (no packing),
// double-buffered. Dynamic smem: 8 tiles of 64x72 bf16 = 73,728 B.
// Writes bf16 hi/lo directly into A slab.
// ---------------------------------------------------------------------------
#define ATTN_SMEM_BYTES (8 * 64 * 72 * 2)

__global__ __launch_bounds__(128) void attn_tc(
    const float* __restrict__ Q)
{
    extern __shared__ __nv_bfloat16 asmem[];
    // tile(buf, arr): arr 0=K0,1=K1,2=V0,3=V1
#define ATILE(b, a) (asmem + ((b) * 4 + (a)) * (64 * 72))

    const int qt   = gridDim.x - 1 - blockIdx.x;
    const int h    = blockIdx.y;
    const int kvh  = h >> 2;
    const int tid  = threadIdx.x;
    const int warp = tid >> 5;
    const int lane = tid & 31;
    const int g = lane >> 2;
    const int t = lane & 3;

    const float scale = 0.125f * 1.44269504088896341f;
    const int r0 = qt * 64 + warp * 16 + g;

    uint32_t qh[4][4], ql[4][4];
    {
        const float* Q0 = Q + (size_t)r0 * QD + h * HD;
        const float* Q1 = Q0 + 8 * QD;
        #pragma unroll
        for (int kd = 0; kd < 4; kd++) {
            float2 p;
            p = *(const float2*)(Q0 + 16 * kd + 2 * t);
            pack_hilo(p.x * scale, p.y * scale, qh[kd][0], ql[kd][0]);
            p = *(const float2*)(Q1 + 16 * kd + 2 * t);
            pack_hilo(p.x * scale, p.y * scale, qh[kd][1], ql[kd][1]);
            p = *(const float2*)(Q0 + 16 * kd + 8 + 2 * t);
            pack_hilo(p.x * scale, p.y * scale, qh[kd][2], ql[kd][2]);
            p = *(const float2*)(Q1 + 16 * kd + 8 + 2 * t);
            pack_hilo(p.x * scale, p.y * scale, qh[kd][3], ql[kd][3]);
        }
    }

    float Oa[8][4];
    #pragma unroll
    for (int nd = 0; nd < 8; nd++)
        #pragma unroll
        for (int r = 0; r < 4; r++) Oa[nd][r] = 0.f;
    float m0 = -1e30f, m1 = -1e30f, l0 = 0.f, l1 = 0.f;

    const int li  = lane & 7;
    const int f_r = ((lane >> 3) & 1) * 8 + li;
    const int f_c = ((lane >> 3) >> 1) * 8;

    // K/V staging: 4 arrays x 64 rows x 8 chunks(16B) = 2048 chunks, 16/thread.
    // arr = i>>2 (compile-time); rem = (i&3)*128 + tid.
    const __nv_bfloat16* kvsrc0 = g_s0 + OFF_K + kvh * HD;  // K hi
    const __nv_bfloat16* kvsrc1 = g_s1 + OFF_K + kvh * HD;  // K lo
    const __nv_bfloat16* kvsrc2 = g_s0 + OFF_V + kvh * HD;  // V hi
    const __nv_bfloat16* kvsrc3 = g_s1 + OFF_V + kvh * HD;  // V lo

#define KV_STAGE(b, kt_) do {                                                  \
        const size_t rowbase = (size_t)(kt_) * 64;                             \
        _Pragma("unroll")                                                      \
        for (int i = 0; i < 16; i++) {                                         \
            const int arr = i >> 2;                                            \
            const int rem = (i & 3) * 128 + tid;                               \
            const int row = rem >> 3;                                          \
            const int chk = rem & 7;                                           \
            const __nv_bfloat16* src =                                         \
                (arr == 0 ? kvsrc0 : arr == 1 ? kvsrc1 :                       \
                 arr == 2 ? kvsrc2 : kvsrc3);                                  \
            cp_async16(ATILE(b, arr) + row * 72 + chk * 8,                     \
                       src + (rowbase + row) * KVD + chk * 8);                 \
        }                                                                      \
    } while (0)

    KV_STAGE(0, 0);
    CP_COMMIT();

    for (int kt = 0; kt <= qt; kt++) {
        const int buf = kt & 1;
        __syncthreads();   // all warps done with buf^1 (prev-prev compute)
        if (kt < qt) {
            KV_STAGE(buf ^ 1, kt + 1);
            CP_COMMIT();
            CP_WAIT(1);
        } else {
            CP_WAIT(0);
        }
        __syncthreads();   // buf data visible to all

        const __nv_bfloat16* Ks0 = ATILE(buf, 0);
        const __nv_bfloat16* Ks1 = ATILE(buf, 1);
        const __nv_bfloat16* Vs0 = ATILE(buf, 2);
        const __nv_bfloat16* Vs1 = ATILE(buf, 3);

        float Sa[8][4];
        #pragma unroll
        for (int nt = 0; nt < 8; nt++)
            #pragma unroll
            for (int r = 0; r < 4; r++) Sa[nt][r] = 0.f;

        #pragma unroll
        for (int kd = 0; kd < 4; kd++) {
            #pragma unroll
            for (int grp = 0; grp < 4; grp++) {
                uint32_t k0r[4], k1r[4];
                ldsm_x4(k0r, Ks0 + (16 * grp + f_r) * 72 + 16 * kd + f_c);
                ldsm_x4(k1r, Ks1 + (16 * grp + f_r) * 72 + 16 * kd + f_c);
                uint32_t b0[2] = {k0r[0], k0r[2]};
                uint32_t b1[2] = {k0r[1], k0r[3]};
                uint32_t c0[2] = {k1r[0], k1r[2]};
                uint32_t c1[2] = {k1r[1], k1r[3]};
                mma_bf16(Sa[2*grp],   qh[kd], b0);
                mma_bf16(Sa[2*grp],   qh[kd], c0);
                mma_bf16(Sa[2*grp],   ql[kd], b0);
                mma_bf16(Sa[2*grp+1], qh[kd], b1);
                mma_bf16(Sa[2*grp+1], qh[kd], c1);
                mma_bf16(Sa[2*grp+1], ql[kd], b1);
            }
        }

        if (kt == qt) {
            const int rl0 = warp * 16 + g, rl1 = rl0 + 8;
            #pragma unroll
            for (int nt = 0; nt < 8; nt++) {
                const int c0 = 8 * nt + 2 * t, c1 = c0 + 1;
                if (c0 > rl0) Sa[nt][0] = -1e30f;
                if (c1 > rl0) Sa[nt][1] = -1e30f;
                if (c0 > rl1) Sa[nt][2] = -1e30f;
                if (c1 > rl1) Sa[nt][3] = -1e30f;
            }
        }

        float mx0 = -1e30f, mx1 = -1e30f;
        #pragma unroll
        for (int nt = 0; nt < 8; nt++) {
            mx0 = fmaxf(mx0, fmaxf(Sa[nt][0], Sa[nt][1]));
            mx1 = fmaxf(mx1, fmaxf(Sa[nt][2], Sa[nt][3]));
        }
        mx0 = fmaxf(mx0, __shfl_xor_sync(0xFFFFFFFFu, mx0, 1));
        mx0 = fmaxf(mx0, __shfl_xor_sync(0xFFFFFFFFu, mx0, 2));
        mx1 = fmaxf(mx1, __shfl_xor_sync(0xFFFFFFFFu, mx1, 1));
        mx1 = fmaxf(mx1, __shfl_xor_sync(0xFFFFFFFFu, mx1, 2));

        const float mn0 = fmaxf(m0, mx0), mn1 = fmaxf(m1, mx1);
        const float al0 = exp2f(m0 - mn0), al1 = exp2f(m1 - mn1);

        float ps0 = 0.f, ps1 = 0.f;
        #pragma unroll
        for (int nt = 0; nt < 8; nt++) {
            Sa[nt][0] = exp2f(Sa[nt][0] - mn0);
            Sa[nt][1] = exp2f(Sa[nt][1] - mn0);
            Sa[nt][2] = exp2f(Sa[nt][2] - mn1);
            Sa[nt][3] = exp2f(Sa[nt][3] - mn1);
            ps0 += Sa[nt][0] + Sa[nt][1];
            ps1 += Sa[nt][2] + Sa[nt][3];
        }
        ps0 += __shfl_xor_sync(0xFFFFFFFFu, ps0, 1);
        ps0 += __shfl_xor_sync(0xFFFFFFFFu, ps0, 2);
        ps1 += __shfl_xor_sync(0xFFFFFFFFu, ps1, 1);
        ps1 += __shfl_xor_sync(0xFFFFFFFFu, ps1, 2);

        l0 = l0 * al0 + ps0;
        l1 = l1 * al1 + ps1;
        #pragma unroll
        for (int nd = 0; nd < 8; nd++) {
            Oa[nd][0] *= al0; Oa[nd][1] *= al0;
            Oa[nd][2] *= al1; Oa[nd][3] *= al1;
        }
        m0 = mn0; m1 = mn1;

        #pragma unroll
        for (int kp = 0; kp < 4; kp++) {
            uint32_t ph[4], pl[4];
            pack_hilo(Sa[2*kp][0],   Sa[2*kp][1],   ph[0], pl[0]);
            pack_hilo(Sa[2*kp][2],   Sa[2*kp][3],   ph[1], pl[1]);
            pack_hilo(Sa[2*kp+1][0], Sa[2*kp+1][1], ph[2], pl[2]);
            pack_hilo(Sa[2*kp+1][2], Sa[2*kp+1][3], ph[3], pl[3]);

            #pragma unroll
            for (int p = 0; p < 4; p++) {
                uint32_t v0r[4], v1r[4];
                ldsm_x4_trans(v0r, Vs0 + (16 * kp + f_r) * 72 + 16 * p + f_c);
                ldsm_x4_trans(v1r, Vs1 + (16 * kp + f_r) * 72 + 16 * p + f_c);
                uint32_t b0[2] = {v0r[0], v0r[1]};
                uint32_t b1[2] = {v0r[2], v0r[3]};
                uint32_t c0[2] = {v1r[0], v1r[1]};
                uint32_t c1[2] = {v1r[2], v1r[3]};
                mma_bf16(Oa[2*p],   ph, b0);
                mma_bf16(Oa[2*p],   ph, c0);
                mma_bf16(Oa[2*p],   pl, b0);
                mma_bf16(Oa[2*p+1], ph, b1);
                mma_bf16(Oa[2*p+1], ph, c1);
                mma_bf16(Oa[2*p+1], pl, b1);
            }
        }
    }
#undef KV_STAGE
#undef ATILE

    const float i0 = 1.f / l0, i1 = 1.f / l1;
    const size_t base = (size_t)OFF_A + (size_t)r0 * QD + h * HD;
    #pragma unroll
    for (int nd = 0; nd < 8; nd++) {
        const int c = 8 * nd + 2 * t;
        uint32_t hi, lo;
        pack_hilo(Oa[nd][0] * i0, Oa[nd][1] * i0, hi, lo);
        *(uint32_t*)(g_s0 + base + c) = hi;
        *(uint32_t*)(g_s1 + base + c) = lo;
        pack_hilo(Oa[nd][2] * i1, Oa[nd][3] * i1, hi, lo);
        *(uint32_t*)(g_s0 + base + 8 * QD + c) = hi;
        *(uint32_t*)(g_s1 + base + 8 * QD + c) = lo;
    }
}

// ---------------------------------------------------------------------------
// Launch
// ---------------------------------------------------------------------------
extern "C" void kernel_launch(void* const* d_in, const int* in_sizes, int n_in,
                              void* d_out, int out_size)
{
    float* out = (float*)d_out;

    float *Qb, *Kb, *Vb;
    cudaGetSymbolAddress((void**)&Qb, g_Q);
    cudaGetSymbolAddress((void**)&Kb, g_K);
    cudaGetSymbolAddress((void**)&Vb, g_V);

    static bool attr_set = false;
    if (!attr_set) {
        cudaFuncSetAttribute(gemm_bf16x3,
                             cudaFuncAttributeMaxDynamicSharedMemorySize,
                             GEMM_SMEM_BYTES);
        cudaFuncSetAttribute(attn_tc,
                             cudaFuncAttributeMaxDynamicSharedMemorySize,
                             ATTN_SMEM_BYTES);
        attr_set = true;
    }

    const float* bigs[4]   = {nullptr, nullptr, nullptr, nullptr};
    const float* smalls[2] = {nullptr, nullptr};
    int nb = 0, ns = 0;
    for (int i = 0; i < n_in && i < 8; i++) {
        if (in_sizes[i] == BIG_N   && nb < 4) bigs[nb++]   = (const float*)d_in[i];
        if (in_sizes[i] == SMALL_N && ns < 2) smalls[ns++] = (const float*)d_in[i];
    }
    if (nb != 4 || ns != 2) {
        bigs[0] = (const float*)d_in[0];
        bigs[1] = (const float*)d_in[1];
        smalls[0] = (const float*)d_in[2];
        smalls[1] = (const float*)d_in[3];
        bigs[2] = (const float*)d_in[4];
        bigs[3] = (const float*)d_in[5];
    }

    classify_kernel<<<1, 32>>>(bigs[0], bigs[1], bigs[2], bigs[3],
                               smalls[0], smalls[1]);

    trig_kernel<<<(S * 32 + 255) / 256, 256>>>();

    // Fused split of all inputs into bf16 (hi, lo) slabs
    split_all_kernel<<<IN_TOTAL / 1024, 256>>>();

    // Fused Q/K/V projections: grid.x = 16 (Q) + 4 (K) + 4 (V)
    gemm_bf16x3<<<dim3(24, S / 128), 256, GEMM_SMEM_BYTES>>>(nullptr, 0);

    // RoPE apply (table-driven)
    rope_apply<<<(S * NH * 32 + 255) / 256, 256>>>(Qb, NH);
    rope_apply<<<(S * NKV * 32 + 255) / 256, 256>>>(Kb, NKV);

    // Split post-rope K/V into bf16 hi/lo slabs
    split_kv_kernel<<<(2 * SMALL_N) / 1024, 256>>>();

    // Attention (cp.async bf16 staging, double-buffered; writes A slab)
    attn_tc<<<dim3(S / 64, NH), 128, ATTN_SMEM_BYTES>>>(Qb);

    // O projection
    gemm_bf16x3<<<dim3(16, S / 128), 256, GEMM_SMEM_BYTES>>>(out, 1);
}

// round 16
// speedup vs baseline: 1.0632x; 1.0632x over previous
#include <cuda_runtime.h>
#include <cuda_bf16.h>
#include <math.h>
#include <stdint.h>

// Problem constants
#define S    2048
#define HID  2048
#define NH   32
#define NKV  8
#define HD   64
#define QD   (NH*HD)    // 2048
#define KVD  (NKV*HD)   // 512

#define BIG_N   (4194304)
#define SMALL_N (1048576)

// Scratch (device globals: allocation-free rule)
__device__ float g_Q[S * QD];
__device__ float g_K[S * KVD];
__device__ float g_V[S * KVD];

// RoPE trig tables
__device__ float g_cos[S * 32];
__device__ float g_sin[S * 32];

// bf16 split slabs. X/Wq/Wk/Wv/Wo/A; roped-K and V slabs at 18M/19M.
#define OFF_X   0
#define OFF_WQ  (4*1024*1024)
#define OFF_WK  (8*1024*1024)
#define OFF_WV  (9*1024*1024)
#define OFF_WO  (10*1024*1024)
#define OFF_A   (14*1024*1024)
#define OFF_K   (18*1024*1024)
#define OFF_V   (19*1024*1024)
#define IN_TOTAL (14*1024*1024)
#define SLAB_N  (20*1024*1024)
__device__ __nv_bfloat16 g_s0[SLAB_N];
__device__ __nv_bfloat16 g_s1[SLAB_N];

// Role table: 0=hidden(X), 1=Wq, 2=Wk, 3=Wv, 4=Wo, 5=Mask
__device__ const float* g_role[6];

// ---------------------------------------------------------------------------
// Input classification (verified rounds 3-15).
// ---------------------------------------------------------------------------
__global__ void classify_kernel(const float* b0, const float* b1,
                                const float* b2, const float* b3,
                                const float* s0, const float* s1)
{
    const int lane = threadIdx.x;
    const float* bigs[4] = {b0, b1, b2, b3};
    float mx[4];
    #pragma unroll
    for (int i = 0; i < 4; i++) {
        float v = fmaxf(fabsf(bigs[i][lane]), fabsf(bigs[i][lane + 32]));
        #pragma unroll
        for (int off = 16; off > 0; off >>= 1)
            v = fmaxf(v, __shfl_xor_sync(0xFFFFFFFFu, v, off));
        mx[i] = v;
    }
    if (lane == 0) {
        int mask_i = -1, hid_i = -1;
        for (int i = 0; i < 4; i++)
            if (bigs[i][0] == 0.0f && bigs[i][1] <= -1e8f) { mask_i = i; break; }
        for (int i = 0; i < 4; i++) {
            if (i == mask_i) continue;
            if (mx[i] > 0.3f) { hid_i = i; break; }
        }
        if (mask_i < 0 || hid_i < 0 || mask_i == hid_i) { hid_i = 0; mask_i = 3; }

        int r0 = -1, r1 = -1;
        for (int i = 0; i < 4; i++)
            if (i != mask_i && i != hid_i) { if (r0 < 0) r0 = i; else r1 = i; }
        int wq_i, wo_i;
        if (hid_i == 0) { wq_i = r0; wo_i = r1; }
        else            { wo_i = r0; wq_i = r1; }

        g_role[0] = bigs[hid_i];
        g_role[1] = bigs[wq_i];
        g_role[2] = s0;
        g_role[3] = s1;
        g_role[4] = bigs[wo_i];
        g_role[5] = bigs[mask_i];
    }
}

// ---------------------------------------------------------------------------
// RoPE trig table.
// ---------------------------------------------------------------------------
__global__ void trig_kernel()
{
    int idx = blockIdx.x * blockDim.x + threadIdx.x;
    if (idx >= S * 32) return;
    int i = idx & 31;
    int s = idx >> 5;
    double invf = pow(10000.0, -(double)(2 * i) / 64.0);
    double ang = (double)s * invf;
    g_cos[idx] = (float)cos(ang);
    g_sin[idx] = (float)sin(ang);
}

// ---------------------------------------------------------------------------
// split helpers
// ---------------------------------------------------------------------------
__device__ __forceinline__ void hilo(float x, __nv_bfloat16& h, __nv_bfloat16& l) {
    h = __float2bfloat16(x);
    l = __float2bfloat16(x - __bfloat162float(h));
}

// ---------------------------------------------------------------------------
// Fused split of ALL inputs into bf16 (hi, lo) slabs.
// ---------------------------------------------------------------------------
__global__ void split_all_kernel()
{
    int idx4 = (blockIdx.x * blockDim.x + threadIdx.x) * 4;
    if (idx4 >= IN_TOTAL) return;
    int role, base;
    if      (idx4 < OFF_WQ) { role = 0; base = OFF_X;  }
    else if (idx4 < OFF_WK) { role = 1; base = OFF_WQ; }
    else if (idx4 < OFF_WV) { role = 2; base = OFF_WK; }
    else if (idx4 < OFF_WO) { role = 3; base = OFF_WV; }
    else                    { role = 4; base = OFF_WO; }
    const float* __restrict__ src = g_role[role] + (idx4 - base);

    float4 x = *(const float4*)src;
    __nv_bfloat162 h01, h23, l01, l23;
    hilo(x.x, h01.x, l01.x); hilo(x.y, h01.y, l01.y);
    hilo(x.z, h23.x, l23.x); hilo(x.w, h23.y, l23.y);
    *(__nv_bfloat162*)(g_s0 + idx4)     = h01;
    *(__nv_bfloat162*)(g_s0 + idx4 + 2) = h23;
    *(__nv_bfloat162*)(g_s1 + idx4)     = l01;
    *(__nv_bfloat162*)(g_s1 + idx4 + 2) = l23;
}

// ---------------------------------------------------------------------------
// Fused K-rope+split and V-split into bf16 hi/lo slabs.
// Blocks [0,2048): K — thread = (s, kv-head, pair i); applies trig rotation.
// Blocks [2048,3072): V — plain 4-elem split.
// ---------------------------------------------------------------------------
__global__ void split_kv_rope_kernel()
{
    const int bid = blockIdx.x;
    if (bid < 2048) {
        int idx = bid * 256 + threadIdx.x;       // 524288 = S*NKV*32
        int i  = idx & 31;
        int t2 = idx >> 5;
        int hk = t2 & 7;
        int s  = t2 >> 3;
        float c  = g_cos[(s << 5) + i];
        float sn = g_sin[(s << 5) + i];
        const float* p = g_K + (size_t)s * KVD + hk * 64;
        float x1 = p[i];
        float x2 = p[i + 32];
        float r1 = x1 * c - x2 * sn;
        float r2 = x2 * c + x1 * sn;
        size_t off = (size_t)OFF_K + (size_t)s * KVD + hk * 64;
        __nv_bfloat16 h, l;
        hilo(r1, h, l); g_s0[off + i]      = h; g_s1[off + i]      = l;
        hilo(r2, h, l); g_s0[off + i + 32] = h; g_s1[off + i + 32] = l;
    } else {
        int idx4 = ((bid - 2048) * 256 + threadIdx.x) * 4;
        if (idx4 >= SMALL_N) return;
        float4 x = *(const float4*)(g_V + idx4);
        __nv_bfloat162 h01, h23, l01, l23;
        hilo(x.x, h01.x, l01.x); hilo(x.y, h01.y, l01.y);
        hilo(x.z, h23.x, l23.x); hilo(x.w, h23.y, l23.y);
        size_t off = (size_t)OFF_V + idx4;
        *(__nv_bfloat162*)(g_s0 + off)     = h01;
        *(__nv_bfloat162*)(g_s0 + off + 2) = h23;
        *(__nv_bfloat162*)(g_s1 + off)     = l01;
        *(__nv_bfloat162*)(g_s1 + off + 2) = l23;
    }
}

// ---------------------------------------------------------------------------
// low-level helpers
// ---------------------------------------------------------------------------
__device__ __forceinline__ uint32_t smem_u32(const void* p) {
    return (uint32_t)__cvta_generic_to_shared(p);
}
__device__ __forceinline__ void cp_async16(void* smem, const void* gmem) {
    asm volatile("cp.async.ca.shared.global [%0], [%1], 16;\n"
                 :: "r"(smem_u32(smem)), "l"(gmem));
}
#define CP_COMMIT()  asm volatile("cp.async.commit_group;\n")
#define CP_WAIT(n)   asm volatile("cp.async.wait_group %0;\n" :: "n"(n))

__device__ __forceinline__ void mma_bf16(float d[4], const uint32_t a[4], const uint32_t b[2])
{
    asm volatile(
        "mma.sync.aligned.m16n8k16.row.col.f32.bf16.bf16.f32 "
        "{%0,%1,%2,%3}, {%4,%5,%6,%7}, {%8,%9}, {%0,%1,%2,%3};\n"
        : "+f"(d[0]), "+f"(d[1]), "+f"(d[2]), "+f"(d[3])
        : "r"(a[0]), "r"(a[1]), "r"(a[2]), "r"(a[3]), "r"(b[0]), "r"(b[1]));
}

__device__ __forceinline__ void ldsm_x4(uint32_t r[4], const void* p) {
    uint32_t s = smem_u32(p);
    asm volatile("ldmatrix.sync.aligned.m8n8.x4.shared.b16 {%0,%1,%2,%3}, [%4];\n"
                 : "=r"(r[0]), "=r"(r[1]), "=r"(r[2]), "=r"(r[3]) : "r"(s));
}
__device__ __forceinline__ void ldsm_x4_trans(uint32_t r[4], const void* p) {
    uint32_t s = smem_u32(p);
    asm volatile("ldmatrix.sync.aligned.m8n8.x4.trans.shared.b16 {%0,%1,%2,%3}, [%4];\n"
                 : "=r"(r[0]), "=r"(r[1]), "=r"(r[2]), "=r"(r[3]) : "r"(s));
}

__device__ __forceinline__ void pack_hilo(float x, float y, uint32_t& hi, uint32_t& lo) {
    __nv_bfloat16 hx = __float2bfloat16(x);
    __nv_bfloat16 hy = __float2bfloat16(y);
    __nv_bfloat162 h = {hx, hy};
    __nv_bfloat162 l;
    l.x = __float2bfloat16(x - __bfloat162float(hx));
    l.y = __float2bfloat16(y - __bfloat162float(hy));
    hi = *(uint32_t*)&h;
    lo = *(uint32_t*)&l;
}

// ---------------------------------------------------------------------------
// bf16x3 GEMM, BK=32, 2-stage cp.async pipeline (verified round 14).
// ---------------------------------------------------------------------------
#define GEMM_SMEM_BYTES ((2*2*128*40 + 2*2*32*136) * 2)   // 75776

__global__ __launch_bounds__(256, 2) void gemm_bf16x3(
    float* outC, int mode)
{
    const int K = HID;
    const __nv_bfloat16 *A0g, *A1g, *B0, *B1;
    float* C;
    int N, cx;
    if (mode == 0) {
        A0g = g_s0 + OFF_X; A1g = g_s1 + OFF_X;
        const int bx = blockIdx.x;
        if (bx < 16)      { B0 = g_s0 + OFF_WQ; B1 = g_s1 + OFF_WQ; C = g_Q; N = QD;  cx = bx; }
        else if (bx < 20) { B0 = g_s0 + OFF_WK; B1 = g_s1 + OFF_WK; C = g_K; N = KVD; cx = bx - 16; }
        else              { B0 = g_s0 + OFF_WV; B1 = g_s1 + OFF_WV; C = g_V; N = KVD; cx = bx - 20; }
    } else {
        A0g = g_s0 + OFF_A; A1g = g_s1 + OFF_A;
        B0 = g_s0 + OFF_WO; B1 = g_s1 + OFF_WO;
        C = outC; N = HID; cx = blockIdx.x;
    }

    extern __shared__ __nv_bfloat16 smem[];
    __nv_bfloat16* AsB = smem;                    // [st][comp][128][40]
    __nv_bfloat16* BsB = smem + 2 * 2 * 128 * 40; // [st][comp][32][136]
#define AS(st, c, r) (AsB + (((st) * 2 + (c)) * 128 + (r)) * 40)
#define BS(st, c, r) (BsB + (((st) * 2 + (c)) * 32  + (r)) * 136)

    const int tid  = threadIdx.x;
    const int lane = tid & 31;
    const int warp = tid >> 5;
    const int wm = warp >> 2;
    const int wn = warp & 3;
    const int g  = lane >> 2;
    const int t  = lane & 3;

    const int am = tid >> 1,  ac = (tid & 1) * 16;
    const int bk = tid >> 3,  bn = (tid & 7) * 8;

    const __nv_bfloat16* Ag0 = A0g + (size_t)(blockIdx.y * 128 + am) * K + ac;
    const __nv_bfloat16* Ag1 = A1g + (size_t)(blockIdx.y * 128 + am) * K + ac;
    const __nv_bfloat16* Bg0 = B0 + (size_t)bk * N + cx * 128 + bn;
    const __nv_bfloat16* Bg1 = B1 + (size_t)bk * N + cx * 128 + bn;

    float acc[4][4][4];
    #pragma unroll
    for (int i = 0; i < 4; i++)
        #pragma unroll
        for (int j = 0; j < 4; j++)
            #pragma unroll
            for (int r = 0; r < 4; r++) acc[i][j][r] = 0.f;

#define STAGE_LOAD(st, kk) do {                                              \
        cp_async16(AS(st, 0, am) + ac,     Ag0 + (kk));                      \
        cp_async16(AS(st, 0, am) + ac + 8, Ag0 + (kk) + 8);                  \
        cp_async16(AS(st, 1, am) + ac,     Ag1 + (kk));                      \
        cp_async16(AS(st, 1, am) + ac + 8, Ag1 + (kk) + 8);                  \
        cp_async16(BS(st, 0, bk) + bn,      Bg0 + (size_t)(kk) * N);         \
        cp_async16(BS(st, 0, bk) + bn + 64, Bg0 + (size_t)(kk) * N + 64);    \
        cp_async16(BS(st, 1, bk) + bn,      Bg1 + (size_t)(kk) * N);         \
        cp_async16(BS(st, 1, bk) + bn + 64, Bg1 + (size_t)(kk) * N + 64);    \
    } while (0)

    STAGE_LOAD(0, 0);
    CP_COMMIT();

    const int li  = lane & 7;
    const int a_r = ((lane >> 3) & 1) * 8 + li;
    const int a_c = ((lane >> 3) >> 1) * 8;
    const int b_r = ((lane >> 3) & 1) * 8 + li;
    const int b_c = ((lane >> 3) >> 1) * 8;

    int buf = 0;
    for (int k0 = 0; k0 < K; k0 += 32, buf ^= 1) {
        if (k0 + 32 < K) {
            STAGE_LOAD(buf ^ 1, k0 + 32);
            CP_COMMIT();
            CP_WAIT(1);
        } else {
            CP_WAIT(0);
        }
        __syncthreads();

        #pragma unroll
        for (int ks = 0; ks < 2; ks++) {
            const int kc = ks * 16;
            uint32_t a0f[4][4], a1f[4][4];
            #pragma unroll
            for (int mt = 0; mt < 4; mt++) {
                const int r = wm * 64 + mt * 16 + a_r;
                ldsm_x4(a0f[mt], AS(buf, 0, r) + kc + a_c);
                ldsm_x4(a1f[mt], AS(buf, 1, r) + kc + a_c);
            }
            uint32_t b0f[4][2], b1f[4][2];
            #pragma unroll
            for (int p = 0; p < 2; p++) {
                const int c = wn * 32 + p * 16 + b_c;
                uint32_t r4[4];
                ldsm_x4_trans(r4, BS(buf, 0, kc + b_r) + c);
                b0f[2*p][0] = r4[0]; b0f[2*p][1] = r4[1];
                b0f[2*p+1][0] = r4[2]; b0f[2*p+1][1] = r4[3];
                ldsm_x4_trans(r4, BS(buf, 1, kc + b_r) + c);
                b1f[2*p][0] = r4[0]; b1f[2*p][1] = r4[1];
                b1f[2*p+1][0] = r4[2]; b1f[2*p+1][1] = r4[3];
            }

            #pragma unroll
            for (int mt = 0; mt < 4; mt++)
                #pragma unroll
                for (int nt = 0; nt < 4; nt++) {
                    mma_bf16(acc[mt][nt], a0f[mt], b0f[nt]);
                    mma_bf16(acc[mt][nt], a0f[mt], b1f[nt]);
                    mma_bf16(acc[mt][nt], a1f[mt], b0f[nt]);
                }
        }
        __syncthreads();
    }
#undef STAGE_LOAD
#undef AS
#undef BS

    #pragma unroll
    for (int mt = 0; mt < 4; mt++)
        #pragma unroll
        for (int nt = 0; nt < 4; nt++) {
            const int r = blockIdx.y * 128 + wm * 64 + mt * 16 + g;
            const int c = cx * 128 + wn * 32 + nt * 8 + 2 * t;
            *(float2*)(C + (size_t)r * N + c)       = make_float2(acc[mt][nt][0], acc[mt][nt][1]);
            *(float2*)(C + (size_t)(r + 8) * N + c) = make_float2(acc[mt][nt][2], acc[mt][nt][3]);
        }
}

// ---------------------------------------------------------------------------
// RoPE apply for Q (table-driven).
// ---------------------------------------------------------------------------
__global__ void rope_apply(float* __restrict__ X, int nheads)
{
    int idx = blockIdx.x * blockDim.x + threadIdx.x;
    if (idx >= S * nheads * 32) return;
    int i = idx & 31;
    int t2 = idx >> 5;
    int h = t2 % nheads;
    int s = t2 / nheads;

    float c  = g_cos[(s << 5) + i];
    float sn = g_sin[(s << 5) + i];

    float* p = X + (size_t)s * (nheads * 64) + h * 64;
    float x1 = p[i];
    float x2 = p[i + 32];
    p[i]      = x1 * c - x2 * sn;
    p[i + 32] = x2 * c + x1 * sn;
}

// ---------------------------------------------------------------------------
// bf16x3 HMMA causal GQA flash attention.
// Static smem (round-14 occupancy); K/V staged from precomputed bf16 hi/lo
// slabs via cp.async (no packing). Writes bf16 hi/lo directly into A slab.
// ---------------------------------------------------------------------------
__global__ __launch_bounds__(128) void attn_tc(
    const float* __restrict__ Q)
{
    const int qt   = gridDim.x - 1 - blockIdx.x;
    const int h    = blockIdx.y;
    const int kvh  = h >> 2;
    const int tid  = threadIdx.x;
    const int warp = tid >> 5;
    const int lane = tid & 31;
    const int g = lane >> 2;
    const int t = lane & 3;

    __shared__ __nv_bfloat16 Ks0[64][72], Ks1[64][72];
    __shared__ __nv_bfloat16 Vs0[64][72], Vs1[64][72];

    const float scale = 0.125f * 1.44269504088896341f;
    const int r0 = qt * 64 + warp * 16 + g;

    uint32_t qh[4][4], ql[4][4];
    {
        const float* Q0 = Q + (size_t)r0 * QD + h * HD;
        const float* Q1 = Q0 + 8 * QD;
        #pragma unroll
        for (int kd = 0; kd < 4; kd++) {
            float2 p;
            p = *(const float2*)(Q0 + 16 * kd + 2 * t);
            pack_hilo(p.x * scale, p.y * scale, qh[kd][0], ql[kd][0]);
            p = *(const float2*)(Q1 + 16 * kd + 2 * t);
            pack_hilo(p.x * scale, p.y * scale, qh[kd][1], ql[kd][1]);
            p = *(const float2*)(Q0 + 16 * kd + 8 + 2 * t);
            pack_hilo(p.x * scale, p.y * scale, qh[kd][2], ql[kd][2]);
            p = *(const float2*)(Q1 + 16 * kd + 8 + 2 * t);
            pack_hilo(p.x * scale, p.y * scale, qh[kd][3], ql[kd][3]);
        }
    }

    float Oa[8][4];
    #pragma unroll
    for (int nd = 0; nd < 8; nd++)
        #pragma unroll
        for (int r = 0; r < 4; r++) Oa[nd][r] = 0.f;
    float m0 = -1e30f, m1 = -1e30f, l0 = 0.f, l1 = 0.f;

    const int li  = lane & 7;
    const int f_r = ((lane >> 3) & 1) * 8 + li;
    const int f_c = ((lane >> 3) >> 1) * 8;

    // K/V slab sources (bf16, post-rope K)
    const __nv_bfloat16* kvsrc0 = g_s0 + OFF_K + kvh * HD;  // K hi
    const __nv_bfloat16* kvsrc1 = g_s1 + OFF_K + kvh * HD;  // K lo
    const __nv_bfloat16* kvsrc2 = g_s0 + OFF_V + kvh * HD;  // V hi
    const __nv_bfloat16* kvsrc3 = g_s1 + OFF_V + kvh * HD;  // V lo

    for (int kt = 0; kt <= qt; kt++) {
        __syncthreads();
        // stage 4 arrays x 64 rows x 8 chunks(16B); 16 chunks per thread
        {
            const size_t rowbase = (size_t)kt * 64;
            #pragma unroll
            for (int i = 0; i < 16; i++) {
                const int arr = i >> 2;
                const int rem = (i & 3) * 128 + tid;
                const int row = rem >> 3;
                const int chk = rem & 7;
                __nv_bfloat16* dst =
                    (arr == 0 ? &Ks0[0][0] : arr == 1 ? &Ks1[0][0] :
                     arr == 2 ? &Vs0[0][0] : &Vs1[0][0]);
                const __nv_bfloat16* src =
                    (arr == 0 ? kvsrc0 : arr == 1 ? kvsrc1 :
                     arr == 2 ? kvsrc2 : kvsrc3);
                cp_async16(dst + row * 72 + chk * 8,
                           src + (rowbase + row) * KVD + chk * 8);
            }
        }
        CP_COMMIT();
        CP_WAIT(0);
        __syncthreads();

        float Sa[8][4];
        #pragma unroll
        for (int nt = 0; nt < 8; nt++)
            #pragma unroll
            for (int r = 0; r < 4; r++) Sa[nt][r] = 0.f;

        #pragma unroll
        for (int kd = 0; kd < 4; kd++) {
            #pragma unroll
            for (int grp = 0; grp < 4; grp++) {
                uint32_t k0r[4], k1r[4];
                ldsm_x4(k0r, &Ks0[16 * grp + f_r][16 * kd + f_c]);
                ldsm_x4(k1r, &Ks1[16 * grp + f_r][16 * kd + f_c]);
                uint32_t b0[2] = {k0r[0], k0r[2]};
                uint32_t b1[2] = {k0r[1], k0r[3]};
                uint32_t c0[2] = {k1r[0], k1r[2]};
                uint32_t c1[2] = {k1r[1], k1r[3]};
                mma_bf16(Sa[2*grp],   qh[kd], b0);
                mma_bf16(Sa[2*grp],   qh[kd], c0);
                mma_bf16(Sa[2*grp],   ql[kd], b0);
                mma_bf16(Sa[2*grp+1], qh[kd], b1);
                mma_bf16(Sa[2*grp+1], qh[kd], c1);
                mma_bf16(Sa[2*grp+1], ql[kd], b1);
            }
        }

        if (kt == qt) {
            const int rl0 = warp * 16 + g, rl1 = rl0 + 8;
            #pragma unroll
            for (int nt = 0; nt < 8; nt++) {
                const int c0 = 8 * nt + 2 * t, c1 = c0 + 1;
                if (c0 > rl0) Sa[nt][0] = -1e30f;
                if (c1 > rl0) Sa[nt][1] = -1e30f;
                if (c0 > rl1) Sa[nt][2] = -1e30f;
                if (c1 > rl1) Sa[nt][3] = -1e30f;
            }
        }

        float mx0 = -1e30f, mx1 = -1e30f;
        #pragma unroll
        for (int nt = 0; nt < 8; nt++) {
            mx0 = fmaxf(mx0, fmaxf(Sa[nt][0], Sa[nt][1]));
            mx1 = fmaxf(mx1, fmaxf(Sa[nt][2], Sa[nt][3]));
        }
        mx0 = fmaxf(mx0, __shfl_xor_sync(0xFFFFFFFFu, mx0, 1));
        mx0 = fmaxf(mx0, __shfl_xor_sync(0xFFFFFFFFu, mx0, 2));
        mx1 = fmaxf(mx1, __shfl_xor_sync(0xFFFFFFFFu, mx1, 1));
        mx1 = fmaxf(mx1, __shfl_xor_sync(0xFFFFFFFFu, mx1, 2));

        const float mn0 = fmaxf(m0, mx0), mn1 = fmaxf(m1, mx1);
        const float al0 = exp2f(m0 - mn0), al1 = exp2f(m1 - mn1);

        float ps0 = 0.f, ps1 = 0.f;
        #pragma unroll
        for (int nt = 0; nt < 8; nt++) {
            Sa[nt][0] = exp2f(Sa[nt][0] - mn0);
            Sa[nt][1] = exp2f(Sa[nt][1] - mn0);
            Sa[nt][2] = exp2f(Sa[nt][2] - mn1);
            Sa[nt][3] = exp2f(Sa[nt][3] - mn1);
            ps0 += Sa[nt][0] + Sa[nt][1];
            ps1 += Sa[nt][2] + Sa[nt][3];
        }
        ps0 += __shfl_xor_sync(0xFFFFFFFFu, ps0, 1);
        ps0 += __shfl_xor_sync(0xFFFFFFFFu, ps0, 2);
        ps1 += __shfl_xor_sync(0xFFFFFFFFu, ps1, 1);
        ps1 += __shfl_xor_sync(0xFFFFFFFFu, ps1, 2);

        l0 = l0 * al0 + ps0;
        l1 = l1 * al1 + ps1;
        #pragma unroll
        for (int nd = 0; nd < 8; nd++) {
            Oa[nd][0] *= al0; Oa[nd][1] *= al0;
            Oa[nd][2] *= al1; Oa[nd][3] *= al1;
        }
        m0 = mn0; m1 = mn1;

        #pragma unroll
        for (int kp = 0; kp < 4; kp++) {
            uint32_t ph[4], pl[4];
            pack_hilo(Sa[2*kp][0],   Sa[2*kp][1],   ph[0], pl[0]);
            pack_hilo(Sa[2*kp][2],   Sa[2*kp][3],   ph[1], pl[1]);
            pack_hilo(Sa[2*kp+1][0], Sa[2*kp+1][1], ph[2], pl[2]);
            pack_hilo(Sa[2*kp+1][2], Sa[2*kp+1][3], ph[3], pl[3]);

            #pragma unroll
            for (int p = 0; p < 4; p++) {
                uint32_t v0r[4], v1r[4];
                ldsm_x4_trans(v0r, &Vs0[16 * kp + f_r][16 * p + f_c]);
                ldsm_x4_trans(v1r, &Vs1[16 * kp + f_r][16 * p + f_c]);
                uint32_t b0[2] = {v0r[0], v0r[1]};
                uint32_t b1[2] = {v0r[2], v0r[3]};
                uint32_t c0[2] = {v1r[0], v1r[1]};
                uint32_t c1[2] = {v1r[2], v1r[3]};
                mma_bf16(Oa[2*p],   ph, b0);
                mma_bf16(Oa[2*p],   ph, c0);
                mma_bf16(Oa[2*p],   pl, b0);
                mma_bf16(Oa[2*p+1], ph, b1);
                mma_bf16(Oa[2*p+1], ph, c1);
                mma_bf16(Oa[2*p+1], pl, b1);
            }
        }
    }

    const float i0 = 1.f / l0, i1 = 1.f / l1;
    const size_t base = (size_t)OFF_A + (size_t)r0 * QD + h * HD;
    #pragma unroll
    for (int nd = 0; nd < 8; nd++) {
        const int c = 8 * nd + 2 * t;
        uint32_t hi, lo;
        pack_hilo(Oa[nd][0] * i0, Oa[nd][1] * i0, hi, lo);
        *(uint32_t*)(g_s0 + base + c) = hi;
        *(uint32_t*)(g_s1 + base + c) = lo;
        pack_hilo(Oa[nd][2] * i1, Oa[nd][3] * i1, hi, lo);
        *(uint32_t*)(g_s0 + base + 8 * QD + c) = hi;
        *(uint32_t*)(g_s1 + base + 8 * QD + c) = lo;
    }
}

// ---------------------------------------------------------------------------
// Launch
// ---------------------------------------------------------------------------
extern "C" void kernel_launch(void* const* d_in, const int* in_sizes, int n_in,
                              void* d_out, int out_size)
{
    float* out = (float*)d_out;

    float *Qb;
    cudaGetSymbolAddress((void**)&Qb, g_Q);

    static bool attr_set = false;
    if (!attr_set) {
        cudaFuncSetAttribute(gemm_bf16x3,
                             cudaFuncAttributeMaxDynamicSharedMemorySize,
                             GEMM_SMEM_BYTES);
        attr_set = true;
    }

    const float* bigs[4]   = {nullptr, nullptr, nullptr, nullptr};
    const float* smalls[2] = {nullptr, nullptr};
    int nb = 0, ns = 0;
    for (int i = 0; i < n_in && i < 8; i++) {
        if (in_sizes[i] == BIG_N   && nb < 4) bigs[nb++]   = (const float*)d_in[i];
        if (in_sizes[i] == SMALL_N && ns < 2) smalls[ns++] = (const float*)d_in[i];
    }
    if (nb != 4 || ns != 2) {
        bigs[0] = (const float*)d_in[0];
        bigs[1] = (const float*)d_in[1];
        smalls[0] = (const float*)d_in[2];
        smalls[1] = (const float*)d_in[3];
        bigs[2] = (const float*)d_in[4];
        bigs[3] = (const float*)d_in[5];
    }

    classify_kernel<<<1, 32>>>(bigs[0], bigs[1], bigs[2], bigs[3],
                               smalls[0], smalls[1]);

    trig_kernel<<<(S * 32 + 255) / 256, 256>>>();

    // Fused split of all inputs into bf16 (hi, lo) slabs
    split_all_kernel<<<IN_TOTAL / 1024, 256>>>();

    // Fused Q/K/V projections: grid.x = 16 (Q) + 4 (K) + 4 (V)
    gemm_bf16x3<<<dim3(24, S / 128), 256, GEMM_SMEM_BYTES>>>(nullptr, 0);

    // RoPE apply on Q (table-driven)
    rope_apply<<<(S * NH * 32 + 255) / 256, 256>>>(Qb, NH);

    // Fused K-rope+split and V-split into bf16 slabs
    split_kv_rope_kernel<<<3072, 256>>>();

    // Attention (static smem, cp.async bf16 staging; writes A slab)
    attn_tc<<<dim3(S / 64, NH), 128>>>(Qb);

    // O projection
    gemm_bf16x3<<<dim3(16, S / 128), 256, GEMM_SMEM_BYTES>>>(out, 1);
}